// round 1
// baseline (speedup 1.0000x reference)
#include <cuda_runtime.h>
#include <math.h>

// Input order (metadata):
// 0: positions  [N*3] f32
// 1: cell       [9]   f32
// 2: sigma_tab  [NS*NS] f32
// 3: eps_tab    [NS*NS] f32
// 4: shift_tab  [NS*NS] f32
// 5: species    [N]   i32
// 6: pair_i     [P]   i32
// 7: pair_j     [P]   i32
// 8: shifts     [P*3] i32
// out: energy [N] f32

__global__ void lj_zero_kernel(float* __restrict__ out, int n) {
    int i = blockIdx.x * blockDim.x + threadIdx.x;
    if (i < n) out[i] = 0.0f;
}

__global__ __launch_bounds__(256)
void lj_pair_kernel(const float* __restrict__ pos,
                    const float* __restrict__ cell,
                    const float* __restrict__ sigma_tab,
                    const float* __restrict__ eps_tab,
                    const float* __restrict__ shift_tab,
                    const int*   __restrict__ species,
                    const int*   __restrict__ pair_i,
                    const int*   __restrict__ pair_j,
                    const int*   __restrict__ shifts,
                    float*       __restrict__ out,
                    int P, int ns) {
    int p = blockIdx.x * blockDim.x + threadIdx.x;
    if (p >= P) return;

    int i = pair_i[p];
    int j = pair_j[p];

    int sx = shifts[3 * p + 0];
    int sy = shifts[3 * p + 1];
    int sz = shifts[3 * p + 2];

    // cell rows (L1-resident broadcast)
    float c00 = cell[0], c01 = cell[1], c02 = cell[2];
    float c10 = cell[3], c11 = cell[4], c12 = cell[5];
    float c20 = cell[6], c21 = cell[7], c22 = cell[8];

    float fx = (float)sx, fy = (float)sy, fz = (float)sz;

    float pix = pos[3 * i + 0], piy = pos[3 * i + 1], piz = pos[3 * i + 2];
    float pjx = pos[3 * j + 0], pjy = pos[3 * j + 1], pjz = pos[3 * j + 2];

    float dx = pjx - pix + fx * c00 + fy * c10 + fz * c20;
    float dy = pjy - piy + fx * c01 + fy * c11 + fz * c21;
    float dz = pjz - piz + fx * c02 + fy * c12 + fz * c22;

    int si = species[i];
    int sj = species[j];
    int t = si * ns + sj;

    float sigma  = sigma_tab[t];
    float eps    = eps_tab[t];
    float shifte = shift_tab[t];

    float r2 = dx * dx + dy * dy + dz * dz;
    float r6 = r2 * r2 * r2;
    float s3 = sigma * sigma * sigma;
    float s6 = s3 * s3;
    float sr6 = s6 / r6;
    float sr12 = sr6 * sr6;
    float e = 4.0f * eps * (sr12 - sr6) - shifte;

    float half = 0.5f * e;
    atomicAdd(out + i, half);
    atomicAdd(out + j, half);
}

extern "C" void kernel_launch(void* const* d_in, const int* in_sizes, int n_in,
                              void* d_out, int out_size) {
    const float* pos       = (const float*)d_in[0];
    const float* cell      = (const float*)d_in[1];
    const float* sigma_tab = (const float*)d_in[2];
    const float* eps_tab   = (const float*)d_in[3];
    const float* shift_tab = (const float*)d_in[4];
    const int*   species   = (const int*)d_in[5];
    const int*   pair_i    = (const int*)d_in[6];
    const int*   pair_j    = (const int*)d_in[7];
    const int*   shifts    = (const int*)d_in[8];
    float*       out       = (float*)d_out;

    int N = in_sizes[5];
    int P = in_sizes[6];
    int ns2 = in_sizes[2];
    int ns = 1;
    while (ns * ns < ns2) ns++;

    lj_zero_kernel<<<(N + 255) / 256, 256>>>(out, N);
    lj_pair_kernel<<<(P + 255) / 256, 256>>>(
        pos, cell, sigma_tab, eps_tab, shift_tab,
        species, pair_i, pair_j, shifts, out, P, ns);
}

// round 2
// speedup vs baseline: 1.4889x; 1.4889x over previous
#include <cuda_runtime.h>
#include <math.h>

// Input order (metadata):
// 0: positions  [N*3] f32
// 1: cell       [9]   f32
// 2: sigma_tab  [NS*NS] f32
// 3: eps_tab    [NS*NS] f32
// 4: shift_tab  [NS*NS] f32
// 5: species    [N]   i32
// 6: pair_i     [P]   i32
// 7: pair_j     [P]   i32
// 8: shifts     [P*3] i32
// out: energy [N] f32

#define MAX_ATOMS 1048576
#define MAX_TAB   64

// packed (x, y, z, species-bits) per atom
__device__ float4 g_posw[MAX_ATOMS];

__global__ void pack_kernel(const float* __restrict__ pos,
                            const int* __restrict__ species, int n) {
    int i = blockIdx.x * blockDim.x + threadIdx.x;
    if (i < n) {
        float4 v;
        v.x = pos[3 * i + 0];
        v.y = pos[3 * i + 1];
        v.z = pos[3 * i + 2];
        v.w = __int_as_float(species[i]);
        g_posw[i] = v;
    }
}

__global__ void lj_zero_kernel(float* __restrict__ out, int n) {
    int i = blockIdx.x * blockDim.x + threadIdx.x;
    if (i < n) out[i] = 0.0f;
}

__global__ __launch_bounds__(256)
void lj_pair_kernel(const float* __restrict__ cell,
                    const float* __restrict__ sigma_tab,
                    const float* __restrict__ eps_tab,
                    const float* __restrict__ shift_tab,
                    const int*   __restrict__ pair_i,
                    const int*   __restrict__ pair_j,
                    const int*   __restrict__ shifts,
                    float*       __restrict__ out,
                    int P, int ns, int ns2) {
    // fused per-species-pair params: (sigma^6, 4*eps, shift_e)
    __shared__ float4 s_par[MAX_TAB];
    if (threadIdx.x < ns2) {
        float sg = sigma_tab[threadIdx.x];
        float s3 = sg * sg * sg;
        s_par[threadIdx.x] = make_float4(s3 * s3, 4.0f * eps_tab[threadIdx.x],
                                         shift_tab[threadIdx.x], 0.0f);
    }
    __syncthreads();

    // cell rows (broadcast, L1-hot)
    const float c00 = cell[0], c01 = cell[1], c02 = cell[2];
    const float c10 = cell[3], c11 = cell[4], c12 = cell[5];
    const float c20 = cell[6], c21 = cell[7], c22 = cell[8];

    const int base = (blockIdx.x * blockDim.x + threadIdx.x) * 4;
    if (base >= P) return;

    int ii[4], jj[4], ss[12];
    if (base + 4 <= P) {
        int4 vi = *reinterpret_cast<const int4*>(pair_i + base);
        int4 vj = *reinterpret_cast<const int4*>(pair_j + base);
        ii[0] = vi.x; ii[1] = vi.y; ii[2] = vi.z; ii[3] = vi.w;
        jj[0] = vj.x; jj[1] = vj.y; jj[2] = vj.z; jj[3] = vj.w;
        const int4* sv = reinterpret_cast<const int4*>(shifts + base * 3);
        int4 s0 = sv[0], s1 = sv[1], s2 = sv[2];
        ss[0] = s0.x; ss[1] = s0.y; ss[2]  = s0.z; ss[3]  = s0.w;
        ss[4] = s1.x; ss[5] = s1.y; ss[6]  = s1.z; ss[7]  = s1.w;
        ss[8] = s2.x; ss[9] = s2.y; ss[10] = s2.z; ss[11] = s2.w;
    } else {
        #pragma unroll
        for (int k = 0; k < 4; k++) {
            int p = base + k;
            if (p < P) {
                ii[k] = pair_i[p]; jj[k] = pair_j[p];
                ss[3 * k + 0] = shifts[3 * p + 0];
                ss[3 * k + 1] = shifts[3 * p + 1];
                ss[3 * k + 2] = shifts[3 * p + 2];
            } else {
                ii[k] = -1; jj[k] = -1;
                ss[3 * k] = ss[3 * k + 1] = ss[3 * k + 2] = 0;
            }
        }
    }

    // issue all gathers up front for MLP
    float4 pwi[4], pwj[4];
    #pragma unroll
    for (int k = 0; k < 4; k++) {
        int i = ii[k] < 0 ? 0 : ii[k];
        int j = jj[k] < 0 ? 0 : jj[k];
        pwi[k] = g_posw[i];
        pwj[k] = g_posw[j];
    }

    #pragma unroll
    for (int k = 0; k < 4; k++) {
        if (ii[k] < 0) continue;
        float fx = (float)ss[3 * k + 0];
        float fy = (float)ss[3 * k + 1];
        float fz = (float)ss[3 * k + 2];

        float dx = pwj[k].x - pwi[k].x + fx * c00 + fy * c10 + fz * c20;
        float dy = pwj[k].y - pwi[k].y + fx * c01 + fy * c11 + fz * c21;
        float dz = pwj[k].z - pwi[k].z + fx * c02 + fy * c12 + fz * c22;

        int si = __float_as_int(pwi[k].w);
        int sj = __float_as_int(pwj[k].w);
        float4 par = s_par[si * ns + sj];

        float r2 = dx * dx + dy * dy + dz * dz;
        float r6 = r2 * r2 * r2;
        float sr6 = __fdividef(par.x, r6);
        float sr12 = sr6 * sr6;
        float e = par.y * (sr12 - sr6) - par.z;

        float half = 0.5f * e;
        atomicAdd(out + ii[k], half);
        atomicAdd(out + jj[k], half);
    }
}

extern "C" void kernel_launch(void* const* d_in, const int* in_sizes, int n_in,
                              void* d_out, int out_size) {
    const float* pos       = (const float*)d_in[0];
    const float* cell      = (const float*)d_in[1];
    const float* sigma_tab = (const float*)d_in[2];
    const float* eps_tab   = (const float*)d_in[3];
    const float* shift_tab = (const float*)d_in[4];
    const int*   species   = (const int*)d_in[5];
    const int*   pair_i    = (const int*)d_in[6];
    const int*   pair_j    = (const int*)d_in[7];
    const int*   shifts    = (const int*)d_in[8];
    float*       out       = (float*)d_out;

    int N = in_sizes[5];
    int P = in_sizes[6];
    int ns2 = in_sizes[2];
    int ns = 1;
    while (ns * ns < ns2) ns++;

    pack_kernel<<<(N + 255) / 256, 256>>>(pos, species, N);
    lj_zero_kernel<<<(N + 255) / 256, 256>>>(out, N);

    int threads = (P + 3) / 4;
    lj_pair_kernel<<<(threads + 255) / 256, 256>>>(
        cell, sigma_tab, eps_tab, shift_tab,
        pair_i, pair_j, shifts, out, P, ns, ns2);
}